// round 9
// baseline (speedup 1.0000x reference)
#include <cuda_runtime.h>
#include <cuda_bf16.h>
#include <math.h>

// ============================================================================
// ControlledSystem RHS (2-mass + controller + Karnopp friction w/ MLP mags).
//
// R7 post-mortem: vec4 is thread-count capped (262K threads < 303K slots ->
// occ ceiling ~86%, measured 77%); T tracks 1/occ (latency-bound).
// R8: vec2 -> 524K threads (2048 blocks), slots stay full until the tail
// wave; v2 loaded first so the dependent table gather issues earliest.
// Table/setup unchanged from measured-best R6/R7.
// ============================================================================

#define TBL 512
#define NNODES (TBL + 1)
#define VMIN (-8.0f)
#define INV_STEP 32.0f           // TBL / 16.0  (range [-8, 8])
#define STEP (1.0f / 32.0f)

// packed table: g_table[i] = (kin_i, sti_i, kin_{i+1}, sti_{i+1})
__device__ __align__(16) float4 g_table[TBL];
__device__ float g_scalars[4];   // K, p_ctrl, K*(z_ctrl - p_ctrl)

// ---------------------------------------------------------------------------

__device__ __forceinline__ float fast_tanh(float x) {
    return 1.0f - 2.0f / (__expf(2.0f * x) + 1.0f);
}

__device__ __forceinline__ float fast_softplus(float x) {
    if (x > 15.0f) return x;
    return log1pf(__expf(x));
}

// One warp per node; lane handles hidden units (lane) and (lane+32).
// Lane 0 writes the node's (kin, sti) into BOTH packed slots that need it.
__global__ void setup_nodes(const float* __restrict__ logK,
                            const float* __restrict__ logz,
                            const float* __restrict__ logp,
                            const float* __restrict__ W1,
                            const float* __restrict__ b1,
                            const float* __restrict__ W2,
                            const float* __restrict__ b2) {
    int gtid = blockIdx.x * blockDim.x + threadIdx.x;
    int node = gtid >> 5;
    int lane = gtid & 31;

    if (gtid == 0) {
        float K  = expf(logK[0]);
        float zc = expf(logz[0]);
        float pc = expf(logp[0]);
        g_scalars[0] = K;
        g_scalars[1] = pc;
        g_scalars[2] = K * (zc - pc);
    }
    if (node >= NNODES) return;

    float v = VMIN + (float)node * STEP;
    float o0 = 0.0f, o1 = 0.0f;
#pragma unroll
    for (int r = 0; r < 2; ++r) {
        int j = lane + 32 * r;
        float h = fast_tanh(fmaf(v, W1[j], b1[j]));
        o0 = fmaf(h, W2[2 * j + 0], o0);
        o1 = fmaf(h, W2[2 * j + 1], o1);
    }
#pragma unroll
    for (int off = 16; off > 0; off >>= 1) {
        o0 += __shfl_down_sync(0xffffffffu, o0, off);
        o1 += __shfl_down_sync(0xffffffffu, o1, off);
    }
    if (lane == 0) {
        float kin = fast_softplus(o0 + b2[0]);
        float sti = fast_softplus(o1 + b2[1]);
        if (node < TBL) {
            g_table[node].x = kin;
            g_table[node].y = sti;
        }
        if (node > 0) {
            g_table[node - 1].z = kin;
            g_table[node - 1].w = sti;
        }
    }
}

// ---------------------------------------------------------------------------
// Per-element physics. M1=1, M2=1.5, K1=2, K2=3, C1=0.5, C2=0.8, dv=0.01,
// x2_ref = 0.5*sin(0.5*t).
// dv1 = u - 5*x1 - 1.3*v1 + 3*x2 + 0.8*v2   (flattened to FMAs)
// ---------------------------------------------------------------------------

__device__ __forceinline__ void rhs_one(float tt, float x1, float v1, float x2,
                                        float v2, float xc,
                                        float K, float pc, float Kzp,
                                        float& d0, float& d1, float& d2,
                                        float& d3, float& d4) {
    float x2r = 0.5f * __sinf(0.5f * tt);
    float e = x2r - x2;
    d4 = fmaf(-pc, xc, e);                 // d_xc
    float u = fmaf(Kzp, xc, K * e);

    d0 = v1;                               // dx1
    float acc = fmaf(-5.0f, x1, u);
    acc = fmaf(-1.3f, v1, acc);
    acc = fmaf(3.0f, x2, acc);
    d1 = fmaf(0.8f, v2, acc);              // dv1 (M1=1)
    d2 = v2;                               // dx2

    float F = fmaf(3.0f, x1 - x2, 0.8f * (v1 - v2));   // F_net

    // friction magnitudes via packed table (post-softplus, linear interp)
    float vcl = fminf(fmaxf(v2, -8.0f), 8.0f);
    float xi = (vcl + 8.0f) * INV_STEP;
    int idx = (int)xi;
    idx = min(idx, TBL - 1);
    float fr = xi - (float)idx;
    float4 ent = __ldg(&g_table[idx]);
    float kin = fmaf(fr, ent.z - ent.x, ent.x);
    float sti = fmaf(fr, ent.w - ent.y, ent.y);

    float Ff = (fabsf(v2) < 0.01f)
                   ? (-fminf(fmaxf(F, -sti), sti))   // static: -clip(F,+/-sti)
                   : (-copysignf(kin, v2));          // kinetic
    d3 = (F + Ff) * (1.0f / 1.5f);         // dv2 (M2=1.5)
}

// ---------------------------------------------------------------------------
// Main streaming kernel, float2 vectorized (requires N % 2 == 0).
// 524288 threads -> thread-slots stay full; v2 loaded FIRST.
// ---------------------------------------------------------------------------

__global__ __launch_bounds__(256, 8) void rhs_kernel_vec2(
    const float* __restrict__ t,
    const float* __restrict__ z,
    float* __restrict__ out, int N) {
    float K   = g_scalars[0];
    float pc  = g_scalars[1];
    float Kzp = g_scalars[2];

    long long i2 = (long long)(blockIdx.x * blockDim.x + threadIdx.x) * 2;
    if (i2 >= N) return;

    long long NN = N;
    // v2 first: the table gather depends on it
    float2 v2v = *(const float2*)(z + 3 * NN + i2);
    float2 tv  = *(const float2*)(t + i2);
    float2 x1v = *(const float2*)(z + i2);
    float2 v1v = *(const float2*)(z + NN + i2);
    float2 x2v = *(const float2*)(z + 2 * NN + i2);
    float2 xcv = *(const float2*)(z + 4 * NN + i2);

    float2 o0, o1, o2, o3, o4;
    rhs_one(tv.x, x1v.x, v1v.x, x2v.x, v2v.x, xcv.x, K, pc, Kzp, o0.x, o1.x, o2.x, o3.x, o4.x);
    rhs_one(tv.y, x1v.y, v1v.y, x2v.y, v2v.y, xcv.y, K, pc, Kzp, o0.y, o1.y, o2.y, o3.y, o4.y);

    *(float2*)(out + i2)          = o0;
    *(float2*)(out + NN + i2)     = o1;
    *(float2*)(out + 2 * NN + i2) = o2;
    *(float2*)(out + 3 * NN + i2) = o3;
    *(float2*)(out + 4 * NN + i2) = o4;
}

// scalar fallback (N % 2 != 0)
__global__ void rhs_kernel_scalar(const float* __restrict__ t,
                                  const float* __restrict__ z,
                                  float* __restrict__ out, int N) {
    float K   = g_scalars[0];
    float pc  = g_scalars[1];
    float Kzp = g_scalars[2];

    long long i = blockIdx.x * blockDim.x + threadIdx.x;
    if (i >= N) return;
    long long NN = N;
    float d0, d1, d2, d3, d4;
    rhs_one(t[i], z[i], z[NN + i], z[2 * NN + i], z[3 * NN + i], z[4 * NN + i],
            K, pc, Kzp, d0, d1, d2, d3, d4);
    out[i]          = d0;
    out[NN + i]     = d1;
    out[2 * NN + i] = d2;
    out[3 * NN + i] = d3;
    out[4 * NN + i] = d4;
}

// ---------------------------------------------------------------------------

extern "C" void kernel_launch(void* const* d_in, const int* in_sizes, int n_in,
                              void* d_out, int out_size) {
    const float* t    = (const float*)d_in[0];
    const float* z    = (const float*)d_in[1];
    const float* logK = (const float*)d_in[2];
    const float* logz = (const float*)d_in[3];
    const float* logp = (const float*)d_in[4];
    const float* W1   = (const float*)d_in[5];
    const float* b1   = (const float*)d_in[6];
    const float* W2   = (const float*)d_in[7];
    const float* b2   = (const float*)d_in[8];
    float* out = (float*)d_out;
    int N = in_sizes[0];

    // one warp per node
    int setup_threads = NNODES * 32;
    setup_nodes<<<(setup_threads + 255) / 256, 256>>>(logK, logz, logp, W1, b1, W2, b2);

    if ((N & 1) == 0) {
        int nthreads = N / 2;
        rhs_kernel_vec2<<<(nthreads + 255) / 256, 256>>>(t, z, out, N);
    } else {
        rhs_kernel_scalar<<<(N + 255) / 256, 256>>>(t, z, out, N);
    }
}

// round 10
// speedup vs baseline: 1.0545x; 1.0545x over previous
#include <cuda_runtime.h>
#include <cuda_bf16.h>
#include <math.h>

// ============================================================================
// ControlledSystem RHS (2-mass + controller + Karnopp friction w/ MLP mags).
//
// R9 post-mortem: vec2 regressed harness time (10.7 -> 13.0us) despite ncu
// improvement; occ pinned ~78% regardless of grid size -> occupancy lever
// exhausted. Revert to R7 vec4 structure (harness-best 10.7us).
// R10: table 512 -> 128 intervals (8KB -> 2KB = 16 L1 lines). The random
// v2 gather touches ~14 distinct lines/warp instead of ~25, cutting the
// L1tex wavefront tax (~207 -> ~116 cyc/warp). Error scales h^2 (measured
// across R1/R4): 9.2e-6 * 16 = 1.5e-4 << 1e-3 threshold.
// ============================================================================

#define TBL 128
#define NNODES (TBL + 1)
#define VMIN (-8.0f)
#define INV_STEP 8.0f            // TBL / 16.0  (range [-8, 8])
#define STEP (1.0f / 8.0f)

// packed table: g_table[i] = (kin_i, sti_i, kin_{i+1}, sti_{i+1})
__device__ __align__(16) float4 g_table[TBL];
__device__ float g_scalars[4];   // K, p_ctrl, K*(z_ctrl - p_ctrl)

// ---------------------------------------------------------------------------

__device__ __forceinline__ float fast_tanh(float x) {
    return 1.0f - 2.0f / (__expf(2.0f * x) + 1.0f);
}

__device__ __forceinline__ float fast_softplus(float x) {
    if (x > 15.0f) return x;
    return log1pf(__expf(x));
}

// One warp per node; lane handles hidden units (lane) and (lane+32).
// Lane 0 writes the node's (kin, sti) into BOTH packed slots that need it.
__global__ void setup_nodes(const float* __restrict__ logK,
                            const float* __restrict__ logz,
                            const float* __restrict__ logp,
                            const float* __restrict__ W1,
                            const float* __restrict__ b1,
                            const float* __restrict__ W2,
                            const float* __restrict__ b2) {
    int gtid = blockIdx.x * blockDim.x + threadIdx.x;
    int node = gtid >> 5;
    int lane = gtid & 31;

    if (gtid == 0) {
        float K  = expf(logK[0]);
        float zc = expf(logz[0]);
        float pc = expf(logp[0]);
        g_scalars[0] = K;
        g_scalars[1] = pc;
        g_scalars[2] = K * (zc - pc);
    }
    if (node >= NNODES) return;

    float v = VMIN + (float)node * STEP;
    float o0 = 0.0f, o1 = 0.0f;
#pragma unroll
    for (int r = 0; r < 2; ++r) {
        int j = lane + 32 * r;
        float h = fast_tanh(fmaf(v, W1[j], b1[j]));
        o0 = fmaf(h, W2[2 * j + 0], o0);
        o1 = fmaf(h, W2[2 * j + 1], o1);
    }
#pragma unroll
    for (int off = 16; off > 0; off >>= 1) {
        o0 += __shfl_down_sync(0xffffffffu, o0, off);
        o1 += __shfl_down_sync(0xffffffffu, o1, off);
    }
    if (lane == 0) {
        float kin = fast_softplus(o0 + b2[0]);
        float sti = fast_softplus(o1 + b2[1]);
        if (node < TBL) {
            g_table[node].x = kin;
            g_table[node].y = sti;
        }
        if (node > 0) {
            g_table[node - 1].z = kin;
            g_table[node - 1].w = sti;
        }
    }
}

// ---------------------------------------------------------------------------
// Per-element physics. M1=1, M2=1.5, K1=2, K2=3, C1=0.5, C2=0.8, dv=0.01,
// x2_ref = 0.5*sin(0.5*t).
// dv1 = u - 5*x1 - 1.3*v1 + 3*x2 + 0.8*v2   (flattened to FMAs)
// ---------------------------------------------------------------------------

__device__ __forceinline__ void rhs_one(float tt, float x1, float v1, float x2,
                                        float v2, float xc,
                                        float K, float pc, float Kzp,
                                        float& d0, float& d1, float& d2,
                                        float& d3, float& d4) {
    float x2r = 0.5f * __sinf(0.5f * tt);
    float e = x2r - x2;
    d4 = fmaf(-pc, xc, e);                 // d_xc
    float u = fmaf(Kzp, xc, K * e);

    d0 = v1;                               // dx1
    float acc = fmaf(-5.0f, x1, u);
    acc = fmaf(-1.3f, v1, acc);
    acc = fmaf(3.0f, x2, acc);
    d1 = fmaf(0.8f, v2, acc);              // dv1 (M1=1)
    d2 = v2;                               // dx2

    float F = fmaf(3.0f, x1 - x2, 0.8f * (v1 - v2));   // F_net

    // friction magnitudes via packed table (post-softplus, linear interp)
    float vcl = fminf(fmaxf(v2, -8.0f), 8.0f);
    float xi = (vcl + 8.0f) * INV_STEP;
    int idx = (int)xi;
    idx = min(idx, TBL - 1);
    float fr = xi - (float)idx;
    float4 ent = __ldg(&g_table[idx]);
    float kin = fmaf(fr, ent.z - ent.x, ent.x);
    float sti = fmaf(fr, ent.w - ent.y, ent.y);

    float Ff = (fabsf(v2) < 0.01f)
                   ? (-fminf(fmaxf(F, -sti), sti))   // static: -clip(F,+/-sti)
                   : (-copysignf(kin, v2));          // kinetic
    d3 = (F + Ff) * (1.0f / 1.5f);         // dv2 (M2=1.5)
}

// ---------------------------------------------------------------------------
// Main streaming kernel, float4 vectorized (requires N % 4 == 0).
// __launch_bounds__(256, 8): 32 regs -> 8 blocks/SM, single wave.
// ---------------------------------------------------------------------------

__global__ __launch_bounds__(256, 8) void rhs_kernel_vec(
    const float* __restrict__ t,
    const float* __restrict__ z,
    float* __restrict__ out, int N) {
    float K   = g_scalars[0];
    float pc  = g_scalars[1];
    float Kzp = g_scalars[2];

    long long i4 = (long long)(blockIdx.x * blockDim.x + threadIdx.x) * 4;
    if (i4 >= N) return;

    long long NN = N;
    float4 t4  = *(const float4*)(t + i4);
    float4 x14 = *(const float4*)(z + i4);
    float4 v14 = *(const float4*)(z + NN + i4);
    float4 x24 = *(const float4*)(z + 2 * NN + i4);
    float4 v24 = *(const float4*)(z + 3 * NN + i4);
    float4 xc4 = *(const float4*)(z + 4 * NN + i4);

    float4 o0, o1, o2, o3, o4;
    rhs_one(t4.x, x14.x, v14.x, x24.x, v24.x, xc4.x, K, pc, Kzp, o0.x, o1.x, o2.x, o3.x, o4.x);
    rhs_one(t4.y, x14.y, v14.y, x24.y, v24.y, xc4.y, K, pc, Kzp, o0.y, o1.y, o2.y, o3.y, o4.y);
    rhs_one(t4.z, x14.z, v14.z, x24.z, v24.z, xc4.z, K, pc, Kzp, o0.z, o1.z, o2.z, o3.z, o4.z);
    rhs_one(t4.w, x14.w, v14.w, x24.w, v24.w, xc4.w, K, pc, Kzp, o0.w, o1.w, o2.w, o3.w, o4.w);

    *(float4*)(out + i4)          = o0;
    *(float4*)(out + NN + i4)     = o1;
    *(float4*)(out + 2 * NN + i4) = o2;
    *(float4*)(out + 3 * NN + i4) = o3;
    *(float4*)(out + 4 * NN + i4) = o4;
}

// scalar fallback (N % 4 != 0)
__global__ void rhs_kernel_scalar(const float* __restrict__ t,
                                  const float* __restrict__ z,
                                  float* __restrict__ out, int N) {
    float K   = g_scalars[0];
    float pc  = g_scalars[1];
    float Kzp = g_scalars[2];

    long long i = blockIdx.x * blockDim.x + threadIdx.x;
    if (i >= N) return;
    long long NN = N;
    float d0, d1, d2, d3, d4;
    rhs_one(t[i], z[i], z[NN + i], z[2 * NN + i], z[3 * NN + i], z[4 * NN + i],
            K, pc, Kzp, d0, d1, d2, d3, d4);
    out[i]          = d0;
    out[NN + i]     = d1;
    out[2 * NN + i] = d2;
    out[3 * NN + i] = d3;
    out[4 * NN + i] = d4;
}

// ---------------------------------------------------------------------------

extern "C" void kernel_launch(void* const* d_in, const int* in_sizes, int n_in,
                              void* d_out, int out_size) {
    const float* t    = (const float*)d_in[0];
    const float* z    = (const float*)d_in[1];
    const float* logK = (const float*)d_in[2];
    const float* logz = (const float*)d_in[3];
    const float* logp = (const float*)d_in[4];
    const float* W1   = (const float*)d_in[5];
    const float* b1   = (const float*)d_in[6];
    const float* W2   = (const float*)d_in[7];
    const float* b2   = (const float*)d_in[8];
    float* out = (float*)d_out;
    int N = in_sizes[0];

    // one warp per node
    int setup_threads = NNODES * 32;
    setup_nodes<<<(setup_threads + 255) / 256, 256>>>(logK, logz, logp, W1, b1, W2, b2);

    if ((N & 3) == 0) {
        int nthreads = N / 4;
        rhs_kernel_vec<<<(nthreads + 255) / 256, 256>>>(t, z, out, N);
    } else {
        rhs_kernel_scalar<<<(N + 255) / 256, 256>>>(t, z, out, N);
    }
}